// round 1
// baseline (speedup 1.0000x reference)
#include <cuda_runtime.h>
#include <cstddef>
#include <math.h>

// ---------------------------------------------------------------------------
// SpatialTranscriptomicsDecoder — fp32 implementation, GB300 sm_103a
// Pipeline: patch proj+LN -> +PE proj -> 4x cross-attn decoder layers -> head
// GEMMs: 64x64x16 tiled SGEMM using packed fma.rn.f32x2 (2 FLOP/lane/instr)
// Attention: warp-per-4-queries, K in smem (transposed), V via L1, softmax in regs
// ---------------------------------------------------------------------------

static constexpr int B = 2, P = 196, FD = 1024, G = 2000, D = 256, H = 8, NL = 4, HALF = 128;
static constexpr float ATT_SCALE = 0.17677669529663687f; // 1/sqrt(32)

// workspace offsets (floats)
static constexpr size_t OFF_PATCH = 0;
static constexpr size_t OFF_TMP   = OFF_PATCH + (size_t)B * P * D;
static constexpr size_t OFF_PE    = OFF_TMP   + (size_t)B * P * D;
static constexpr size_t OFF_KV    = OFF_PE    + (size_t)B * P * D;
static constexpr size_t OFF_Q     = OFF_KV    + (size_t)B * P * 2 * D;
static constexpr size_t OFF_QB    = OFF_Q     + (size_t)B * G * D;
static constexpr size_t OFF_CTX   = OFF_QB    + (size_t)B * G * D;
static constexpr size_t OFF_ATT   = OFF_CTX   + (size_t)B * G * D;
static constexpr size_t OFF_FFH   = OFF_ATT   + (size_t)B * G * D;
static constexpr size_t OFF_QP    = OFF_FFH   + (size_t)B * G * 4 * D;
static constexpr size_t OFF_PP    = OFF_QP    + (size_t)B * G * HALF;
static constexpr size_t WS_TOTAL  = OFF_PP    + (size_t)B * P * HALF;

__device__ float g_ws[WS_TOTAL];

__device__ __forceinline__ float geluf(float x) {
    return 0.5f * x * (1.0f + erff(x * 0.7071067811865476f));
}
__device__ __forceinline__ float softplusf(float x) {
    return fmaxf(x, 0.0f) + __logf(1.0f + __expf(-fabsf(x)));
}
__device__ __forceinline__ float2 u2f2(unsigned long long u) {
    float2 f;
    asm("mov.b64 {%0, %1}, %2;" : "=f"(f.x), "=f"(f.y) : "l"(u));
    return f;
}

// ---------------------------------------------------------------------------
// C[M,N] = act( A[M,K] @ W[N,K]^T + bias[N] + (R ? R[M,N] : 0) )
// Requires N % 64 == 0, K % 16 == 0 (true for every call here).
// act: 0 = none, 1 = exact GELU
// ---------------------------------------------------------------------------
__global__ void __launch_bounds__(256) sgemm_kernel(
    const float* __restrict__ A, const float* __restrict__ W,
    const float* __restrict__ bias, const float* __restrict__ R,
    float* __restrict__ C, int M, int N, int K, int act)
{
    __shared__ __align__(16) float As[64][20];
    __shared__ __align__(16) float Ws[16][68];
    const int tid = threadIdx.x;
    const int tx = tid & 15;        // -> N
    const int ty = tid >> 4;        // -> M
    const int bm = blockIdx.y * 64;
    const int bn = blockIdx.x * 64;
    const int lr = tid >> 2;        // 0..63 tile row for loads
    const int lc = (tid & 3) << 2;  // 0,4,8,12 k-offset
    const bool a_ok = (bm + lr) < M;
    const float* Ap = A + (size_t)(bm + lr) * K + lc;
    const float* Wp = W + (size_t)(bn + lr) * K + lc;

    unsigned long long acc[4][2];
#pragma unroll
    for (int i = 0; i < 4; i++) { acc[i][0] = 0ull; acc[i][1] = 0ull; }

    for (int k0 = 0; k0 < K; k0 += 16) {
        float4 av = a_ok ? *(const float4*)(Ap + k0) : make_float4(0.f, 0.f, 0.f, 0.f);
        float4 wv = *(const float4*)(Wp + k0);
        __syncthreads();
        *(float4*)&As[lr][lc] = av;
        Ws[lc + 0][lr] = wv.x;
        Ws[lc + 1][lr] = wv.y;
        Ws[lc + 2][lr] = wv.z;
        Ws[lc + 3][lr] = wv.w;
        __syncthreads();
#pragma unroll
        for (int kk = 0; kk < 16; kk++) {
            ulonglong2 bb = *(const ulonglong2*)&Ws[kk][tx << 2];
#pragma unroll
            for (int i = 0; i < 4; i++) {
                float a = As[(ty << 2) + i][kk];
                unsigned long long a2;
                asm("mov.b64 %0, {%1, %1};" : "=l"(a2) : "f"(a));
                asm("fma.rn.f32x2 %0, %1, %2, %0;" : "+l"(acc[i][0]) : "l"(a2), "l"(bb.x));
                asm("fma.rn.f32x2 %0, %1, %2, %0;" : "+l"(acc[i][1]) : "l"(a2), "l"(bb.y));
            }
        }
    }

    const int col0 = bn + (tx << 2);
    float4 b4 = make_float4(0.f, 0.f, 0.f, 0.f);
    if (bias) b4 = *(const float4*)(bias + col0);
#pragma unroll
    for (int i = 0; i < 4; i++) {
        int row = bm + (ty << 2) + i;
        if (row >= M) continue;
        float2 v0 = u2f2(acc[i][0]);
        float2 v1 = u2f2(acc[i][1]);
        float4 o;
        o.x = v0.x + b4.x; o.y = v0.y + b4.y; o.z = v1.x + b4.z; o.w = v1.y + b4.w;
        if (R) {
            float4 r4 = *(const float4*)(R + (size_t)row * N + col0);
            o.x += r4.x; o.y += r4.y; o.z += r4.z; o.w += r4.w;
        }
        if (act == 1) {
            o.x = geluf(o.x); o.y = geluf(o.y); o.z = geluf(o.z); o.w = geluf(o.w);
        }
        *(float4*)(C + (size_t)row * N + col0) = o;
    }
}

// ---------------------------------------------------------------------------
// y[row] = LayerNorm( x[row] + (r ? r[row] : 0) ) * g + b, width 256
// One warp per row.
// ---------------------------------------------------------------------------
__global__ void ln_kernel(const float* __restrict__ x, const float* __restrict__ r,
                          const float* __restrict__ gg, const float* __restrict__ bb,
                          float* __restrict__ y, int rows)
{
    int gid = blockIdx.x * blockDim.x + threadIdx.x;
    int row = gid >> 5;
    int lane = gid & 31;
    if (row >= rows) return;
    const float* xp = x + (size_t)row * 256;
    float4 a = *(const float4*)(xp + lane * 4);
    float4 c = *(const float4*)(xp + 128 + lane * 4);
    if (r) {
        const float* rp = r + (size_t)row * 256;
        float4 ra = *(const float4*)(rp + lane * 4);
        float4 rc = *(const float4*)(rp + 128 + lane * 4);
        a.x += ra.x; a.y += ra.y; a.z += ra.z; a.w += ra.w;
        c.x += rc.x; c.y += rc.y; c.z += rc.z; c.w += rc.w;
    }
    float s = a.x + a.y + a.z + a.w + c.x + c.y + c.z + c.w;
    float q = a.x * a.x + a.y * a.y + a.z * a.z + a.w * a.w
            + c.x * c.x + c.y * c.y + c.z * c.z + c.w * c.w;
#pragma unroll
    for (int o = 16; o; o >>= 1) {
        s += __shfl_xor_sync(0xffffffffu, s, o);
        q += __shfl_xor_sync(0xffffffffu, q, o);
    }
    float mean = s * (1.f / 256.f);
    float var = q * (1.f / 256.f) - mean * mean;
    float rstd = rsqrtf(var + 1e-5f);
    float4 g0 = *(const float4*)(gg + lane * 4);
    float4 g1 = *(const float4*)(gg + 128 + lane * 4);
    float4 b0 = *(const float4*)(bb + lane * 4);
    float4 b1 = *(const float4*)(bb + 128 + lane * 4);
    float4 o0, o1;
    o0.x = (a.x - mean) * rstd * g0.x + b0.x;
    o0.y = (a.y - mean) * rstd * g0.y + b0.y;
    o0.z = (a.z - mean) * rstd * g0.z + b0.z;
    o0.w = (a.w - mean) * rstd * g0.w + b0.w;
    o1.x = (c.x - mean) * rstd * g1.x + b1.x;
    o1.y = (c.y - mean) * rstd * g1.y + b1.y;
    o1.z = (c.z - mean) * rstd * g1.z + b1.z;
    o1.w = (c.w - mean) * rstd * g1.w + b1.w;
    float* yp = y + (size_t)row * 256;
    *(float4*)(yp + lane * 4) = o0;
    *(float4*)(yp + 128 + lane * 4) = o1;
}

// ---------------------------------------------------------------------------
// pe[b,p,:] = concat(row_embed[r], col_embed[c])
// ---------------------------------------------------------------------------
__global__ void pe_kernel(const int* __restrict__ coords, const float* __restrict__ re,
                          const float* __restrict__ ce, float* __restrict__ pe)
{
    int idx = blockIdx.x * blockDim.x + threadIdx.x;
    if (idx >= B * P * D) return;
    int d = idx & 255;
    int bp = idx >> 8;
    int r = coords[bp * 2 + 0];
    int c = coords[bp * 2 + 1];
    r = min(max(r, 0), 255);
    c = min(max(c, 0), 255);
    pe[idx] = (d < 128) ? re[r * 128 + d] : ce[c * 128 + (d - 128)];
}

// q[b,g,:] = gene_queries[g,:]
__global__ void qinit_kernel(const float* __restrict__ gq, float* __restrict__ q)
{
    int idx = blockIdx.x * blockDim.x + threadIdx.x;
    if (idx >= B * G * D) return;
    q[idx] = gq[idx % (G * D)];
}

// ---------------------------------------------------------------------------
// Cross-attention: grid (B*H, ceil(G/32)), block 256 (8 warps, 4 queries/warp)
// Q: [B*G, 256], KV: [B*P, 512] (K cols 0..255, V cols 256..511) -> ctx [B*G,256]
// scale folded into K. 196 keys -> 7 per lane, softmax in registers.
// ---------------------------------------------------------------------------
__global__ void __launch_bounds__(256) attn_kernel(
    const float* __restrict__ Q, const float* __restrict__ KV, float* __restrict__ ctx)
{
    __shared__ float Kt[32][196];  // K transposed: Kt[d][p]
    const int bh = blockIdx.x;
    const int b = bh >> 3, h = bh & 7;
    const int tid = threadIdx.x;
    const int lane = tid & 31, w = tid >> 5;

    const float* KVb = KV + (size_t)b * P * 512;
    for (int i = tid; i < P * 32; i += 256) {
        int p = i >> 5, d = i & 31;
        Kt[d][p] = KVb[(size_t)p * 512 + h * 32 + d] * ATT_SCALE;
    }
    __syncthreads();

    const int g0 = (blockIdx.y * 8 + w) * 4;
    if (g0 >= G) return;  // uniform per warp; no further barriers below

    float qr[4];
#pragma unroll
    for (int i = 0; i < 4; i++)
        qr[i] = Q[(size_t)(b * G + g0 + i) * 256 + h * 32 + lane];

    float sc[4][7];
#pragma unroll
    for (int i = 0; i < 4; i++)
#pragma unroll
        for (int j = 0; j < 7; j++) sc[i][j] = 0.f;

#pragma unroll 4
    for (int d = 0; d < 32; d++) {
        float k0 = Kt[d][lane];
        float k1 = Kt[d][32 + lane];
        float k2 = Kt[d][64 + lane];
        float k3 = Kt[d][96 + lane];
        float k4 = Kt[d][128 + lane];
        float k5 = Kt[d][160 + lane];
        float k6 = (lane < 4) ? Kt[d][192 + lane] : 0.f;
#pragma unroll
        for (int i = 0; i < 4; i++) {
            float qd = __shfl_sync(0xffffffffu, qr[i], d);
            sc[i][0] = fmaf(qd, k0, sc[i][0]);
            sc[i][1] = fmaf(qd, k1, sc[i][1]);
            sc[i][2] = fmaf(qd, k2, sc[i][2]);
            sc[i][3] = fmaf(qd, k3, sc[i][3]);
            sc[i][4] = fmaf(qd, k4, sc[i][4]);
            sc[i][5] = fmaf(qd, k5, sc[i][5]);
            sc[i][6] = fmaf(qd, k6, sc[i][6]);
        }
    }

    // softmax over 196 keys per query (invalid tail lanes masked to -inf)
#pragma unroll
    for (int i = 0; i < 4; i++) {
        if (lane >= 4) sc[i][6] = -1e30f;
        float m = sc[i][0];
#pragma unroll
        for (int j = 1; j < 7; j++) m = fmaxf(m, sc[i][j]);
#pragma unroll
        for (int o = 16; o; o >>= 1) m = fmaxf(m, __shfl_xor_sync(0xffffffffu, m, o));
        float s = 0.f;
#pragma unroll
        for (int j = 0; j < 7; j++) { float e = __expf(sc[i][j] - m); sc[i][j] = e; s += e; }
#pragma unroll
        for (int o = 16; o; o >>= 1) s += __shfl_xor_sync(0xffffffffu, s, o);
        float inv = 1.0f / s;
#pragma unroll
        for (int j = 0; j < 7; j++) sc[i][j] *= inv;
    }

    // ctx[d=lane] = sum_k attn[k] * V[k][d]; attn broadcast via shuffles
    float cx[4] = {0.f, 0.f, 0.f, 0.f};
    const float* Vb = KVb + 256 + h * 32 + lane;
#pragma unroll
    for (int jj = 0; jj < 7; jj++) {
        const int kmax = (jj == 6) ? 4 : 32;
        for (int src = 0; src < kmax; src++) {
            float v = Vb[(size_t)(jj * 32 + src) * 512];
#pragma unroll
            for (int i = 0; i < 4; i++) {
                float a = __shfl_sync(0xffffffffu, sc[i][jj], src);
                cx[i] = fmaf(a, v, cx[i]);
            }
        }
    }
#pragma unroll
    for (int i = 0; i < 4; i++)
        ctx[(size_t)(b * G + g0 + i) * 256 + h * 32 + lane] = cx[i];
}

// ---------------------------------------------------------------------------
// out[b,p,g,:] = softplus(q_proj[b,g,:] + p_proj[b,p,:])   (bias folded in q_proj)
// grid (250, 392), block 256: 8 genes per block, float4 over HALF=128
// ---------------------------------------------------------------------------
__global__ void __launch_bounds__(256) head_kernel(
    const float* __restrict__ qp, const float* __restrict__ pp, float* __restrict__ out)
{
    const int bp = blockIdx.y;
    const int b = (bp >= P) ? 1 : 0;
    const int g = blockIdx.x * 8 + (threadIdx.x >> 5);
    const int hh = (threadIdx.x & 31) << 2;
    float4 pv = *(const float4*)(pp + (size_t)bp * HALF + hh);
    float4 qv = *(const float4*)(qp + (size_t)(b * G + g) * HALF + hh);
    float4 o;
    o.x = softplusf(pv.x + qv.x);
    o.y = softplusf(pv.y + qv.y);
    o.z = softplusf(pv.z + qv.z);
    o.w = softplusf(pv.w + qv.w);
    *(float4*)(out + ((size_t)bp * G + g) * HALF + hh) = o;
}

// ---------------------------------------------------------------------------
// host side
// ---------------------------------------------------------------------------
static inline void sgemm(const float* A, const float* W, const float* bias, const float* R,
                         float* C, int M, int N, int K, int act)
{
    dim3 grid(N / 64, (M + 63) / 64);
    sgemm_kernel<<<grid, 256>>>(A, W, bias, R, C, M, N, K, act);
}

static inline void ln(const float* x, const float* r, const float* g, const float* b,
                      float* y, int rows)
{
    ln_kernel<<<(rows + 7) / 8, 256>>>(x, r, g, b, y, rows);
}

extern "C" void kernel_launch(void* const* d_in, const int* in_sizes, int n_in,
                              void* d_out, int out_size)
{
    (void)in_sizes; (void)n_in; (void)out_size;
    const float* patch_features = (const float*)d_in[0];
    const int*   patch_coords   = (const int*)d_in[1];
    const float* patch_proj_w   = (const float*)d_in[2];
    const float* patch_proj_b   = (const float*)d_in[3];
    const float* patch_ln_g     = (const float*)d_in[4];
    const float* patch_ln_b     = (const float*)d_in[5];
    const float* row_embed      = (const float*)d_in[6];
    const float* col_embed      = (const float*)d_in[7];
    const float* pe_proj_w      = (const float*)d_in[8];
    const float* pe_proj_b      = (const float*)d_in[9];
    const float* gene_queries   = (const float*)d_in[10];
    const float* in_proj_w      = (const float*)d_in[11];
    const float* in_proj_b      = (const float*)d_in[12];
    const float* out_w          = (const float*)d_in[13];
    const float* out_b          = (const float*)d_in[14];
    const float* ff1_w          = (const float*)d_in[15];
    const float* ff1_b          = (const float*)d_in[16];
    const float* ff2_w          = (const float*)d_in[17];
    const float* ff2_b          = (const float*)d_in[18];
    const float* ln1_g          = (const float*)d_in[19];
    const float* ln1_b          = (const float*)d_in[20];
    const float* ln2_g          = (const float*)d_in[21];
    const float* ln2_b          = (const float*)d_in[22];
    const float* head_w1        = (const float*)d_in[23];
    const float* head_b1        = (const float*)d_in[24];
    float* out = (float*)d_out;

    float* ws = nullptr;
    cudaGetSymbolAddress((void**)&ws, g_ws);
    float* patch_emb = ws + OFF_PATCH;
    float* tmp       = ws + OFF_TMP;
    float* pe        = ws + OFF_PE;
    float* kv        = ws + OFF_KV;
    float* q         = ws + OFF_Q;
    float* Qb        = ws + OFF_QB;
    float* ctx       = ws + OFF_CTX;
    float* att       = ws + OFF_ATT;
    float* ffh       = ws + OFF_FFH;
    float* qproj     = ws + OFF_QP;
    float* pproj     = ws + OFF_PP;

    const int MQ = B * G;  // 4000
    const int MP = B * P;  // 392

    // Stage A: patch embedding
    sgemm(patch_features, patch_proj_w, patch_proj_b, nullptr, tmp, MP, D, FD, 0);
    ln(tmp, nullptr, patch_ln_g, patch_ln_b, patch_emb, MP);
    pe_kernel<<<(B * P * D + 255) / 256, 256>>>(patch_coords, row_embed, col_embed, pe);
    sgemm(pe, pe_proj_w, pe_proj_b, patch_emb, patch_emb, MP, D, D, 0);
    qinit_kernel<<<(B * G * D + 255) / 256, 256>>>(gene_queries, q);

    // Stage B: decoder layers
    for (int l = 0; l < NL; l++) {
        const float* Wq  = in_proj_w + (size_t)l * 3 * D * D;
        const float* Wkv = Wq + (size_t)D * D;
        const float* bq  = in_proj_b + (size_t)l * 3 * D;
        const float* bkv = bq + D;
        sgemm(q, Wq, bq, nullptr, Qb, MQ, D, D, 0);
        sgemm(patch_emb, Wkv, bkv, nullptr, kv, MP, 2 * D, D, 0);
        attn_kernel<<<dim3(B * H, (G + 31) / 32), 256>>>(Qb, kv, ctx);
        sgemm(ctx, out_w + (size_t)l * D * D, out_b + (size_t)l * D, nullptr, att, MQ, D, D, 0);
        ln(q, att, ln1_g + (size_t)l * D, ln1_b + (size_t)l * D, q, MQ);
        sgemm(q, ff1_w + (size_t)l * 4 * D * D, ff1_b + (size_t)l * 4 * D, nullptr, ffh, MQ, 4 * D, D, 1);
        sgemm(ffh, ff2_w + (size_t)l * D * 4 * D, ff2_b + (size_t)l * D, nullptr, att, MQ, D, 4 * D, 0);
        ln(q, att, ln2_g + (size_t)l * D, ln2_b + (size_t)l * D, q, MQ);
    }

    // Stage C: head + broadcast softplus epilogue
    sgemm(q, head_w1, head_b1, nullptr, qproj, MQ, HALF, D, 0);
    sgemm(patch_emb, head_w1, nullptr, nullptr, pproj, MP, HALF, D, 0);
    head_kernel<<<dim3(G / 8, B * P), 256>>>(qproj, pproj, out);
}